// round 1
// baseline (speedup 1.0000x reference)
#include <cuda_runtime.h>
#include <cuda_bf16.h>
#include <math.h>

// Problem constants
#define VOCAB 50000
#define E 256
#define S 512
#define BATCH 4
#define ROWS (BATCH * S)          // 2048
#define E2 (2 * E)                // 512
#define LOGITS_ELEMS ((long long)ROWS * VOCAB)  // 102,400,000
#define OUT_CONCEPT_OFF LOGITS_ELEMS
#define OUT_STRUCT_OFF (LOGITS_ELEMS + BATCH * 32)

// ---------------- scratch (device globals; no allocs allowed) ----------------
__device__ float g_hker[E];               // circular conv kernel (256)
__device__ float g_dw1f[E * E2];          // folded dw1: [256,512]
__device__ float g_cw1f[E * E];           // folded cw1: [256,256]
__device__ float g_xs[ROWS * E];          // spectral-filtered signal [2048,256]
__device__ float g_c1[ROWS * E];          // concept hidden 1
__device__ float g_c2[ROWS * 64];         // concept hidden 2
__device__ float g_meanc2[BATCH * 64];    // per-batch mean of c2
__device__ float g_h1[ROWS * E2];         // decoder hidden 1 [2048,512]
__device__ float g_h2[ROWS * E];          // decoder hidden 2 [2048,256]

// ---------------- init: spectral kernel h[d] ----------------
// x4 = tile(x,4) is 256-periodic => FFT_1024 nonzero only at k=4m.
// y[n] = sum_j |x[j]| * h[(n-j) mod 256],
// h[d] = (1/256) sum_m cos(ang_m + 2*pi*m*d/256), ang_m = 1.5*atan(ln(k_m+1e-6)),
// k_m = |fftfreq(1024)*1024| at index 4m = (m<=128 ? 4m : 1024-4m).
__global__ void init_hker_kernel() {
    int d = threadIdx.x;  // 0..255
    double acc = 0.0;
    for (int m = 0; m < 256; m++) {
        int k = (m <= 128) ? 4 * m : 1024 - 4 * m;
        double ang = 1.5 * atan(log((double)k + 1e-6));
        int p = (m * d) & 255;
        acc += cos(ang + 2.0 * M_PI * (double)p / 256.0);
    }
    g_hker[d] = (float)(acc / 256.0);
}

// ---------------- fold tiled-input weights: W' = W0+W1+W2+W3 ----------------
__global__ void fold_weights_kernel(const float* __restrict__ dw1,
                                    const float* __restrict__ cw1) {
    int i = blockIdx.x * blockDim.x + threadIdx.x;
    if (i < E * E2) {
        int j = i / E2, o = i % E2;
        g_dw1f[i] = dw1[j * E2 + o] + dw1[(j + 256) * E2 + o] +
                    dw1[(j + 512) * E2 + o] + dw1[(j + 768) * E2 + o];
    }
    if (i < E * E) {
        int j = i / E, o = i % E;
        g_cw1f[i] = cw1[j * E + o] + cw1[(j + 256) * E + o] +
                    cw1[(j + 512) * E + o] + cw1[(j + 768) * E + o];
    }
}

// ---------------- gather + spectral filter (circular conv) ----------------
__global__ void spectral_kernel(const int* __restrict__ ids,
                                const float* __restrict__ emb) {
    int row = blockIdx.x;       // 0..2047
    int n = threadIdx.x;        // 0..255
    __shared__ float sa[E];
    __shared__ float sh[E];
    int cid = ids[row];
    float x = emb[(long long)cid * E + n];
    float a = fabsf(x);
    float sgn = (x > 0.f) ? 1.f : ((x < 0.f) ? -1.f : 0.f);
    sa[n] = a;
    sh[n] = g_hker[n];
    __syncthreads();
    float acc = 0.f;
#pragma unroll 16
    for (int j = 0; j < 256; j++) {
        acc += sa[j] * sh[(n - j) & 255];
    }
    g_xs[row * E + n] = acc * sgn;
}

// ---------------- generic tiled SGEMM: C = act(A[M,K] @ B[K,N] + bias) ------
// ACT: 0 = none, 1 = relu, 2 = exact gelu
template <int ACT>
__global__ void __launch_bounds__(256)
sgemm128_kernel(const float* __restrict__ A, const float* __restrict__ B,
                const float* __restrict__ bias, float* __restrict__ C,
                int M, int N, int K) {
    const int BK = 8, TM = 8, TN = 8;
    __shared__ float As[BK][128];
    __shared__ float Bs[BK][128];

    int tid = threadIdx.x;
    int tcol = tid % 16;     // 16 thread-cols over N
    int trow = tid / 16;     // 16 thread-rows over M
    int arow = tid / 2;      // A-load row in tile (0..127)
    int acol = (tid % 2) * 4;
    int brow = tid / 32;     // B-load row in tile (0..7)
    int bcol = (tid % 32) * 4;

    int nbase = blockIdx.x * 128;
    const float* Ab = A + (long long)blockIdx.y * 128 * K;

    float acc[TM][TN];
#pragma unroll
    for (int i = 0; i < TM; i++)
#pragma unroll
        for (int j = 0; j < TN; j++) acc[i][j] = 0.f;

    for (int k0 = 0; k0 < K; k0 += BK) {
        float4 av = *(const float4*)(Ab + (long long)arow * K + k0 + acol);
        As[acol + 0][arow] = av.x;
        As[acol + 1][arow] = av.y;
        As[acol + 2][arow] = av.z;
        As[acol + 3][arow] = av.w;

        float4 bv = make_float4(0.f, 0.f, 0.f, 0.f);
        if (nbase + bcol < N)   // N % 4 == 0 for all our shapes
            bv = *(const float4*)(B + (long long)(k0 + brow) * N + nbase + bcol);
        *(float4*)&Bs[brow][bcol] = bv;
        __syncthreads();

        float ar[TM], br[TN];
#pragma unroll
        for (int kk = 0; kk < BK; kk++) {
#pragma unroll
            for (int i = 0; i < TM; i++) ar[i] = As[kk][trow * TM + i];
#pragma unroll
            for (int j = 0; j < TN; j++) br[j] = Bs[kk][tcol * TN + j];
#pragma unroll
            for (int i = 0; i < TM; i++)
#pragma unroll
                for (int j = 0; j < TN; j++) acc[i][j] += ar[i] * br[j];
        }
        __syncthreads();
    }

#pragma unroll
    for (int i = 0; i < TM; i++) {
        long long r = (long long)blockIdx.y * 128 + trow * TM + i;
#pragma unroll
        for (int j = 0; j < TN; j++) {
            int c = nbase + tcol * TN + j;
            if (c < N) {
                float v = acc[i][j] + bias[c];
                if (ACT == 1) v = fmaxf(v, 0.f);
                else if (ACT == 2) v = 0.5f * v * (1.f + erff(v * 0.70710678118654752f));
                C[r * N + c] = v;
            }
        }
    }
}

// ---------------- layernorm over last dim (512), in place ----------------
__global__ void layernorm_kernel(float* __restrict__ h,
                                 const float* __restrict__ gamma,
                                 const float* __restrict__ beta) {
    int row = blockIdx.x;
    float* p = h + (long long)row * E2;
    int t = threadIdx.x;  // 256 threads, 2 elems each
    float v0 = p[t], v1 = p[t + 256];

    __shared__ float red[8];
    __shared__ float bc;
    // sum
    float s = v0 + v1;
#pragma unroll
    for (int o = 16; o > 0; o >>= 1) s += __shfl_down_sync(0xffffffffu, s, o);
    if ((t & 31) == 0) red[t >> 5] = s;
    __syncthreads();
    if (t < 32) {
        float v = (t < 8) ? red[t] : 0.f;
#pragma unroll
        for (int o = 4; o > 0; o >>= 1) v += __shfl_down_sync(0xffffffffu, v, o);
        if (t == 0) bc = v;
    }
    __syncthreads();
    float mu = bc * (1.f / 512.f);
    __syncthreads();
    // variance
    float d0 = v0 - mu, d1 = v1 - mu;
    float q = d0 * d0 + d1 * d1;
#pragma unroll
    for (int o = 16; o > 0; o >>= 1) q += __shfl_down_sync(0xffffffffu, q, o);
    if ((t & 31) == 0) red[t >> 5] = q;
    __syncthreads();
    if (t < 32) {
        float v = (t < 8) ? red[t] : 0.f;
#pragma unroll
        for (int o = 4; o > 0; o >>= 1) v += __shfl_down_sync(0xffffffffu, v, o);
        if (t == 0) bc = v;
    }
    __syncthreads();
    float rstd = rsqrtf(bc * (1.f / 512.f) + 1e-5f);
    p[t] = d0 * rstd * gamma[t] + beta[t];
    p[t + 256] = d1 * rstd * gamma[t + 256] + beta[t + 256];
}

// ---------------- concept mean over seq ----------------
__global__ void mean_c2_kernel() {
    int b = blockIdx.x;     // 0..3
    int o = threadIdx.x;    // 0..63
    float s = 0.f;
    for (int t = 0; t < S; t++) s += g_c2[(long long)(b * S + t) * 64 + o];
    g_meanc2[b * 64 + o] = s * (1.f / (float)S);
}

// ---------------- tiny head: concept_vector + structure_probs ----------------
__global__ void head_kernel(const float* __restrict__ cw3, const float* __restrict__ cb3,
                            const float* __restrict__ sw1, const float* __restrict__ sb1,
                            const float* __restrict__ sw2, const float* __restrict__ sb2,
                            float* __restrict__ out) {
    __shared__ float cv[BATCH * 32];
    __shared__ float t1[BATCH * 16];
    int t = threadIdx.x;  // 128 threads
    {
        int b = t / 32, n = t % 32;
        float acc = cb3[n];
        for (int k = 0; k < 64; k++) acc += g_meanc2[b * 64 + k] * cw3[k * 32 + n];
        cv[b * 32 + n] = acc;
        out[OUT_CONCEPT_OFF + b * 32 + n] = acc;
    }
    __syncthreads();
    if (t < BATCH * 16) {
        int b = t / 16, n = t % 16;
        float acc = sb1[n];
        for (int k = 0; k < 32; k++) acc += cv[b * 32 + k] * sw1[k * 16 + n];
        t1[b * 16 + n] = fmaxf(acc, 0.f);
    }
    __syncthreads();
    if (t < BATCH * 8) {
        int b = t / 8, n = t % 8;
        float acc = sb2[n];
        for (int k = 0; k < 16; k++) acc += t1[b * 16 + k] * sw2[k * 8 + n];
        out[OUT_STRUCT_OFF + b * 8 + n] = 1.f / (1.f + expf(-acc));
    }
}

// ---------------- launch ----------------
extern "C" void kernel_launch(void* const* d_in, const int* in_sizes, int n_in,
                              void* d_out, int out_size) {
    const int*   char_ids = (const int*)d_in[0];
    const float* emb  = (const float*)d_in[1];
    const float* dw1  = (const float*)d_in[2];
    const float* db1  = (const float*)d_in[3];
    const float* ln_g = (const float*)d_in[4];
    const float* ln_b = (const float*)d_in[5];
    const float* dw2  = (const float*)d_in[6];
    const float* db2  = (const float*)d_in[7];
    const float* dw3  = (const float*)d_in[8];
    const float* db3  = (const float*)d_in[9];
    const float* cw1  = (const float*)d_in[10];
    const float* cb1  = (const float*)d_in[11];
    const float* cw2  = (const float*)d_in[12];
    const float* cb2  = (const float*)d_in[13];
    const float* cw3  = (const float*)d_in[14];
    const float* cb3  = (const float*)d_in[15];
    const float* sw1  = (const float*)d_in[16];
    const float* sb1  = (const float*)d_in[17];
    const float* sw2  = (const float*)d_in[18];
    const float* sb2  = (const float*)d_in[19];
    float* out = (float*)d_out;

    // resolve device-global scratch addresses
    float *p_xs, *p_c1, *p_c2, *p_h1, *p_h2, *p_dw1f, *p_cw1f;
    cudaGetSymbolAddress((void**)&p_xs,   g_xs);
    cudaGetSymbolAddress((void**)&p_c1,   g_c1);
    cudaGetSymbolAddress((void**)&p_c2,   g_c2);
    cudaGetSymbolAddress((void**)&p_h1,   g_h1);
    cudaGetSymbolAddress((void**)&p_h2,   g_h2);
    cudaGetSymbolAddress((void**)&p_dw1f, g_dw1f);
    cudaGetSymbolAddress((void**)&p_cw1f, g_cw1f);

    init_hker_kernel<<<1, 256>>>();
    fold_weights_kernel<<<(E * E2 + 255) / 256, 256>>>(dw1, cw1);
    spectral_kernel<<<ROWS, 256>>>(char_ids, emb);

    // concept path
    sgemm128_kernel<1><<<dim3(E / 128, ROWS / 128), 256>>>(p_xs, p_cw1f, cb1, p_c1, ROWS, E, E);
    sgemm128_kernel<1><<<dim3(1, ROWS / 128), 256>>>(p_c1, cw2, cb2, p_c2, ROWS, 64, E);
    mean_c2_kernel<<<BATCH, 64>>>();
    head_kernel<<<1, 128>>>(cw3, cb3, sw1, sb1, sw2, sb2, out);

    // decoder path
    sgemm128_kernel<2><<<dim3(E2 / 128, ROWS / 128), 256>>>(p_xs, p_dw1f, db1, p_h1, ROWS, E2, E);
    layernorm_kernel<<<ROWS, 256>>>(p_h1, ln_g, ln_b);
    sgemm128_kernel<2><<<dim3(E / 128, ROWS / 128), 256>>>(p_h1, dw2, db2, p_h2, ROWS, E, E2);
    sgemm128_kernel<0><<<dim3((VOCAB + 127) / 128, ROWS / 128), 256>>>(p_h2, dw3, db3, out, ROWS, VOCAB, E);
}